// round 17
// baseline (speedup 1.0000x reference)
#include <cuda_runtime.h>
#include <cstdint>

#define N_NODES 100000
#define N_EDGES 1600000
#define D_EDGE  50
#define SLOTS   64            // fixed eid slots per node (binomial max degree ~40)
#define STAGE   32            // slots staged in SMEM (P(cnt>32) ~ 1e-4)
#define NPB     10            // nodes per block (10 groups of 25 threads)

__device__ int g_cnt[N_NODES];
__device__ int g_slot[(size_t)N_NODES * SLOTS];  // 25.6MB
__device__ int g_ovf_n;                          // overflow count (expected 0)
__device__ int g_ovf[N_EDGES];

// Thread-local dtype detect: interpret first 8 words as int64. True int64
// indices all lie in [0,N_NODES); int32 data packed pairwise has a high half
// that is itself a random index (nonzero w.p. 1-1e-5 per word) -> blows the
// range. Used only on the ~never-taken overflow path.
__device__ __forceinline__ bool detect_i64_local(const void* __restrict__ recv) {
    const long long* p64 = (const long long*)recv;
    int bad = 0;
#pragma unroll
    for (int i = 0; i < 8; i++) {
        long long v = p64[i];
        if (v < 0 || v >= N_NODES) bad = 1;
    }
    return bad == 0;
}

// ---------------------------------------------------------------------------
// Kernel 1: build slot lists. Each block self-detects the receivers dtype
// from the first 64 int64-interpreted words (L1/L2-cached, ~free) -- no
// separate init kernel, no global flag. 4 independent edges per thread so
// the atomicAdd(result)->store chains overlap (ATOMG latency ~318 cyc).
// ---------------------------------------------------------------------------
__global__ void build_kernel(const void* __restrict__ recv) {
    __shared__ int s_bad;
    const int tid = threadIdx.x;
    if (tid == 0) s_bad = 0;
    __syncthreads();
    {
        const long long* p64 = (const long long*)recv;
        if (tid < 64) {
            long long v = p64[tid];
            if (v < 0 || v >= N_NODES) s_bad = 1;   // benign racy write of 1
        }
    }
    __syncthreads();
    const bool is64 = (s_bad == 0);

    const int T = blockDim.x;
    const int base = blockIdx.x * T * 4 + tid;

    int e[4], r[4], pos[4];
    bool ok[4];
#pragma unroll
    for (int k = 0; k < 4; k++) {
        e[k] = base + k * T;
        ok[k] = (e[k] < N_EDGES);
        if (ok[k]) {
            long long rr = is64 ? ((const long long*)recv)[e[k]]
                                : (long long)((const int*)recv)[e[k]];
            ok[k] = ((unsigned long long)rr < (unsigned long long)N_NODES);
            r[k] = (int)rr;
        }
    }
#pragma unroll
    for (int k = 0; k < 4; k++) {
        if (ok[k]) pos[k] = atomicAdd(&g_cnt[r[k]], 1);
    }
#pragma unroll
    for (int k = 0; k < 4; k++) {
        if (!ok[k]) continue;
        if (pos[k] < SLOTS) g_slot[(size_t)r[k] * SLOTS + pos[k]] = e[k];
        else                g_ovf[atomicAdd(&g_ovf_n, 1)] = e[k];
    }
}

// ---------------------------------------------------------------------------
// Kernel 2: gather, 25-thread groups (10 nodes per 256-thread block); every
// participating thread owns a real float2 dim-pair (no idle lanes). Only the
// first STAGE=32 slots are staged in SMEM (saves 12.8MB of staging reads);
// the ~10 nodes chip-wide with cnt>32 read the tail from global. Edge rows
// streamed with __ldcs (touched once -> keep L2 clean), 4-way unroll for MLP.
// Overflow fixup fused (expected no-op; local dtype detect). Writes every
// output row exactly once -> no output zeroing anywhere.
// ---------------------------------------------------------------------------
__global__ void gather_kernel(const float* __restrict__ edges,
                              const void* __restrict__ recv,
                              float* __restrict__ out) {
    __shared__ int s_eid[NPB][STAGE];
    __shared__ int s_cnt[NPB];

    const int tid = threadIdx.x;
    const int node_base = blockIdx.x * NPB;

    if (tid < NPB) {
        const int node = node_base + tid;
        s_cnt[tid] = (node < N_NODES) ? g_cnt[node] : 0;
    }
    for (int i = tid; i < NPB * STAGE; i += blockDim.x) {
        const int g = i >> 5;              // / STAGE
        const int s = i & (STAGE - 1);
        const int node = node_base + g;
        if (node < N_NODES) s_eid[g][s] = g_slot[(size_t)node * SLOTS + s];
    }
    __syncthreads();

    const int group = tid / 25;
    const int gl = tid - group * 25;
    if (group >= NPB) return;
    const int node = node_base + group;
    if (node >= N_NODES) return;

    const int cnt_raw = s_cnt[group];
    const int cnt = (cnt_raw < SLOTS) ? cnt_raw : SLOTS;
    const int c1 = (cnt < STAGE) ? cnt : STAGE;
    const int d = 2 * gl;

    float2 a0 = make_float2(0.f, 0.f), a1 = make_float2(0.f, 0.f);
    float2 a2 = make_float2(0.f, 0.f), a3 = make_float2(0.f, 0.f);

    int j = 0;
    for (; j + 4 <= c1; j += 4) {
        const int e0 = s_eid[group][j + 0];
        const int e1 = s_eid[group][j + 1];
        const int e2 = s_eid[group][j + 2];
        const int e3 = s_eid[group][j + 3];
        float2 v0 = __ldcs(reinterpret_cast<const float2*>(edges + (size_t)e0 * D_EDGE + d));
        float2 v1 = __ldcs(reinterpret_cast<const float2*>(edges + (size_t)e1 * D_EDGE + d));
        float2 v2 = __ldcs(reinterpret_cast<const float2*>(edges + (size_t)e2 * D_EDGE + d));
        float2 v3 = __ldcs(reinterpret_cast<const float2*>(edges + (size_t)e3 * D_EDGE + d));
        a0.x += v0.x; a0.y += v0.y;
        a1.x += v1.x; a1.y += v1.y;
        a2.x += v2.x; a2.y += v2.y;
        a3.x += v3.x; a3.y += v3.y;
    }
    for (; j < c1; j++) {
        const int e = s_eid[group][j];
        float2 v = __ldcs(reinterpret_cast<const float2*>(edges + (size_t)e * D_EDGE + d));
        a0.x += v.x; a0.y += v.y;
    }
    // rare tail: slots [STAGE, cnt) straight from global (P ~ 1e-4 per node)
    for (; j < cnt; j++) {
        const int e = g_slot[(size_t)node * SLOTS + j];
        float2 v = __ldcs(reinterpret_cast<const float2*>(edges + (size_t)e * D_EDGE + d));
        a0.x += v.x; a0.y += v.y;
    }

    // fused overflow fixup: only nodes that actually overflowed scan the list
    if (cnt_raw > SLOTS) {
        const bool is64 = detect_i64_local(recv);
        const int n = g_ovf_n;
        for (int o = 0; o < n; o++) {
            const int e = g_ovf[o];
            long long rr = is64 ? ((const long long*)recv)[e]
                                : (long long)((const int*)recv)[e];
            if ((int)rr == node) {
                float2 v = *reinterpret_cast<const float2*>(edges + (size_t)e * D_EDGE + d);
                a0.x += v.x; a0.y += v.y;
            }
        }
    }

    float2 r = make_float2((a0.x + a1.x) + (a2.x + a3.x),
                           (a0.y + a1.y) + (a2.y + a3.y));
    *reinterpret_cast<float2*>(out + (size_t)node * D_EDGE + d) = r;
}

extern "C" void kernel_launch(void* const* d_in, const int* in_sizes, int n_in,
                              void* d_out, int out_size) {
    // Identify inputs by element count (robust to ordering):
    //   nodes: 800,000 f32 (unused) | edges: 80,000,000 f32 | receivers: 1,600,000
    const float* edges = nullptr;
    const void* receivers = nullptr;
    for (int i = 0; i < n_in; i++) {
        if (in_sizes[i] == N_EDGES * D_EDGE) {
            edges = (const float*)d_in[i];
        } else if (in_sizes[i] == N_EDGES) {
            receivers = d_in[i];
        }
    }
    float* out = (float*)d_out;

    // Zero counters via graph-capturable memset nodes (no kernel launch cost).
    void* p_cnt = nullptr;
    void* p_ovf = nullptr;
    cudaGetSymbolAddress(&p_cnt, g_cnt);
    cudaGetSymbolAddress(&p_ovf, g_ovf_n);
    cudaMemsetAsync(p_cnt, 0, sizeof(int) * N_NODES);
    cudaMemsetAsync(p_ovf, 0, sizeof(int));

    const int T = 256;

    // 1) build per-node slot lists (per-block dtype self-detect, 4-edge ILP)
    build_kernel<<<(N_EDGES + T * 4 - 1) / (T * 4), T>>>(receivers);

    // 2) gather: 10 nodes per block, 25 threads per node, fused overflow
    gather_kernel<<<(N_NODES + NPB - 1) / NPB, T>>>(edges, receivers, out);
}